// round 4
// baseline (speedup 1.0000x reference)
#include <cuda_runtime.h>
#include <cuda_fp16.h>
#include <cstdint>

// Problem geometry: velocity (B=2, D=128, H=128, W=128, C=3) float32
#define B_  2
#define DIM 128
#define VOX_PER_B (DIM * DIM * DIM)          // 2097152 = 1<<21
#define N_VOX (B_ * VOX_PER_B)               // 4194304

// Ping-pong scratch: 8 B/voxel = (half2(vz,vy), half2(vx,0)) packed in uint2
__device__ uint2 g_bufA[N_VOX];
__device__ uint2 g_bufB[N_VOX];

static __device__ __forceinline__ uint2 pack_v(float vz, float vy, float vx)
{
    __half2 h0 = __floats2half2_rn(vz, vy);
    __half2 h1 = __floats2half2_rn(vx, 0.f);
    uint2 r;
    r.x = *(const unsigned int*)&h0;
    r.y = *(const unsigned int*)&h1;
    return r;
}

static __device__ __forceinline__ void unpack_v(uint2 r, float& vz, float& vy, float& vx)
{
    __half2 h0 = *(const __half2*)&r.x;
    __half2 h1 = *(const __half2*)&r.y;
    float2 f0 = __half22float2(h0);
    vz = f0.x; vy = f0.y;
    vx = __low2float(h1);
}

// -------- convert: float3 AoS fp32 input -> packed fp16, fused 1/2^STEPS scale --------
__global__ __launch_bounds__(256)
void convert_kernel(const float* __restrict__ in, uint2* __restrict__ out, float s)
{
    int t = blockIdx.x * blockDim.x + threadIdx.x;   // one thread = 4 voxels
    if (t >= N_VOX / 4) return;
    const float4* in4 = (const float4*)in;
    float4 a = in4[t * 3 + 0];
    float4 b = in4[t * 3 + 1];
    float4 c = in4[t * 3 + 2];
    out[t * 4 + 0] = pack_v(a.x * s, a.y * s, a.z * s);
    out[t * 4 + 1] = pack_v(a.w * s, b.x * s, b.y * s);
    out[t * 4 + 2] = pack_v(b.z * s, b.w * s, c.x * s);
    out[t * 4 + 3] = pack_v(c.y * s, c.z * s, c.w * s);
}

// -------- tiled squaring step: 8x8x8 tile + halo H in shared memory --------
// LAST=0: write packed fp16 scratch. LAST=1: write stride-3 fp32 output + identity grid.
template <int H, int LAST>
__global__ __launch_bounds__(256)
void gridexp_tile(const uint2* __restrict__ src, uint2* __restrict__ dst,
                  float* __restrict__ dst3)
{
    constexpr int TS = 8;
    constexpr int XS = TS + 2 * H;           // tile+halo extent per dim
    constexpr int YS = XS, ZS = XS;
    constexpr int SMEM_N = ZS * YS * XS;
    __shared__ uint2 s[SMEM_N];

    const int bx = blockIdx.x, by = blockIdx.y;
    const int bz = blockIdx.z & 15;
    const int b  = blockIdx.z >> 4;
    const int base = b << 21;

    const int x0b = bx * TS - H;             // tile-with-halo origin (may be negative)
    const int y0b = by * TS - H;
    const int z0b = bz * TS - H;

    // cooperative coalesced tile+halo load (wrapped)
    for (int i = threadIdx.x; i < SMEM_N; i += 256) {
        int sz = i / (YS * XS);
        int rem = i - sz * (YS * XS);
        int sy = rem / XS;
        int sx = rem - sy * XS;
        int gz = (z0b + sz) & 127;
        int gy = (y0b + sy) & 127;
        int gx = (x0b + sx) & 127;
        s[i] = __ldg(src + (base + (gz << 14) + (gy << 7) + gx));
    }
    __syncthreads();

    const int tx = threadIdx.x & 3;          // x-pair index 0..3
    const int ty = (threadIdx.x >> 2) & 7;
    const int tz = threadIdx.x >> 5;

    const int gz = bz * TS + tz;
    const int gy = by * TS + ty;
    const int gx0 = bx * TS + 2 * tx;

    float oz[2], oy[2], ox[2];

#pragma unroll
    for (int vi = 0; vi < 2; ++vi) {
        const int lx = 2 * tx + vi;
        const int gx = gx0 + vi;

        uint2 pv = s[((tz + H) * YS + (ty + H)) * XS + (lx + H)];
        float vz, vy, vx;
        unpack_v(pv, vz, vy, vx);

        float phz = (float)gz + vz;
        float phy = (float)gy + vy;
        float phx = (float)gx + vx;

        float fz = floorf(phz), fy = floorf(phy), fx = floorf(phx);
        float wz1 = phz - fz, wy1 = phy - fy, wx1 = phx - fx;
        float wz0 = 1.0f - wz1, wy0 = 1.0f - wy1, wx0 = 1.0f - wx1;
        float wz[2] = { wz0, wz1 };
        float wy[2] = { wy0, wy1 };
        float wx[2] = { wx0, wx1 };

        int iz = (int)fz, iy = (int)fy, ix = (int)fx;
        int lz0 = iz - z0b, ly0 = iy - y0b, lx0 = ix - x0b;

        float az = 0.f, ay = 0.f, ax = 0.f;

        if (lz0 >= 0 && lz0 < ZS - 1 &&
            ly0 >= 0 && ly0 < YS - 1 &&
            lx0 >= 0 && lx0 < XS - 1) {
            // fast path: all 8 corners inside the smem tile
#pragma unroll
            for (int a = 0; a < 2; ++a) {
#pragma unroll
                for (int c = 0; c < 2; ++c) {
                    float wzy = wz[a] * wy[c];
                    int rowoff = ((lz0 + a) * YS + (ly0 + c)) * XS + lx0;
#pragma unroll
                    for (int d = 0; d < 2; ++d) {
                        uint2 q = s[rowoff + d];
                        float qz, qy, qx;
                        unpack_v(q, qz, qy, qx);
                        float w = wzy * wx[d];
                        az += w * qz; ay += w * qy; ax += w * qx;
                    }
                }
            }
        } else {
            // rare fallback: wrapped global gather (always correct)
            int z0 = iz & 127, z1 = (z0 + 1) & 127;
            int y0 = iy & 127, y1 = (y0 + 1) & 127;
            int x0 = ix & 127, x1 = (x0 + 1) & 127;
            int zo[2] = { z0 << 14, z1 << 14 };
            int yo[2] = { y0 << 7,  y1 << 7  };
            int xo[2] = { x0,       x1       };
#pragma unroll
            for (int a = 0; a < 2; ++a) {
#pragma unroll
                for (int c = 0; c < 2; ++c) {
                    float wzy = wz[a] * wy[c];
                    int zy = base + zo[a] + yo[c];
#pragma unroll
                    for (int d = 0; d < 2; ++d) {
                        uint2 q = __ldg(src + zy + xo[d]);
                        float qz, qy, qx;
                        unpack_v(q, qz, qy, qx);
                        float w = wzy * wx[d];
                        az += w * qz; ay += w * qy; ax += w * qx;
                    }
                }
            }
        }

        oz[vi] = vz + az;
        oy[vi] = vy + ay;
        ox[vi] = vx + ax;
    }

    const int idx = base + (gz << 14) + (gy << 7) + gx0;   // even

    if (LAST) {
        float* o = dst3 + (size_t)idx * 3;                  // 8B aligned
        ((float2*)o)[0] = make_float2(oz[0] + (float)gz, oy[0] + (float)gy);
        ((float2*)o)[1] = make_float2(ox[0] + (float)gx0, oz[1] + (float)gz);
        ((float2*)o)[2] = make_float2(oy[1] + (float)gy, ox[1] + (float)(gx0 + 1));
    } else {
        uint2 p0 = pack_v(oz[0], oy[0], ox[0]);
        uint2 p1 = pack_v(oz[1], oy[1], ox[1]);
        ((uint4*)dst)[idx >> 1] = make_uint4(p0.x, p0.y, p1.x, p1.y);
    }
}

extern "C" void kernel_launch(void* const* d_in, const int* in_sizes, int n_in,
                              void* d_out, int out_size)
{
    (void)in_sizes; (void)n_in; (void)out_size;
    const float* vel = (const float*)d_in[0];
    float* out = (float*)d_out;

    uint2* bufA = nullptr;
    uint2* bufB = nullptr;
    cudaGetSymbolAddress((void**)&bufA, g_bufA);
    cudaGetSymbolAddress((void**)&bufB, g_bufB);

    const float scale = 1.0f / 256.0f;   // 1 / 2^STEPS, STEPS = 8
    const int threads = 256;

    convert_kernel<<<(N_VOX / 4 + threads - 1) / threads, threads>>>(vel, bufA, scale);

    dim3 grid(16, 16, 32);               // 16^3 tiles x 2 batches
    uint2* cur = bufA;
    uint2* nxt = bufB;

    // steps 0-4: |v| <= ~0.41  -> halo 1
    for (int i = 0; i < 5; ++i) {
        gridexp_tile<1, 0><<<grid, threads>>>(cur, nxt, nullptr);
        uint2* t = cur; cur = nxt; nxt = t;
    }
    // steps 5-6: |v| <= ~1.63  -> halo 2
    for (int i = 0; i < 2; ++i) {
        gridexp_tile<2, 0><<<grid, threads>>>(cur, nxt, nullptr);
        uint2* t = cur; cur = nxt; nxt = t;
    }
    // step 7 (last): |v| <= ~3.25 -> halo 4, fused identity-grid add + fp32 output
    gridexp_tile<4, 1><<<grid, threads>>>(cur, nullptr, out);
}

// round 5
// speedup vs baseline: 1.3736x; 1.3736x over previous
#include <cuda_runtime.h>
#include <cuda_fp16.h>
#include <cstdint>

// Problem geometry: velocity (B=2, D=128, H=128, W=128, C=3) float32
#define B_  2
#define DIM 128
#define VOX_PER_B (DIM * DIM * DIM)          // 2097152 = 1<<21
#define N_VOX (B_ * VOX_PER_B)               // 4194304

// Ping-pong scratch: 8 B/voxel = (half2(vz,vy), half2(vx,0)) packed in uint2
__device__ uint2 g_bufA[N_VOX];
__device__ uint2 g_bufB[N_VOX];

static __device__ __forceinline__ uint2 pack_v(float vz, float vy, float vx)
{
    __half2 h0 = __floats2half2_rn(vz, vy);
    __half2 h1 = __floats2half2_rn(vx, 0.f);
    uint2 r;
    r.x = *(const unsigned int*)&h0;
    r.y = *(const unsigned int*)&h1;
    return r;
}

// -------- convert: float3 AoS fp32 input -> packed fp16, fused 1/2^STEPS scale --------
__global__ __launch_bounds__(256)
void convert_kernel(const float* __restrict__ in, uint2* __restrict__ out, float s)
{
    int t = blockIdx.x * blockDim.x + threadIdx.x;   // one thread = 4 voxels
    if (t >= N_VOX / 4) return;
    const float4* in4 = (const float4*)in;
    float4 a = in4[t * 3 + 0];
    float4 b = in4[t * 3 + 1];
    float4 c = in4[t * 3 + 2];
    out[t * 4 + 0] = pack_v(a.x * s, a.y * s, a.z * s);
    out[t * 4 + 1] = pack_v(a.w * s, b.x * s, b.y * s);
    out[t * 4 + 2] = pack_v(b.z * s, b.w * s, c.x * s);
    out[t * 4 + 3] = pack_v(c.y * s, c.z * s, c.w * s);
}

// -------- one squaring step: fp16 storage, half2 gather math, fp32 own-value math --------
// LAST=0: dst (packed fp16 scratch). LAST=1: dst3 (stride-3 fp32 output) + identity grid.
template <int LAST>
__global__ __launch_bounds__(256)
void gridexp_step(const uint2* __restrict__ src, uint2* __restrict__ dst,
                  float* __restrict__ dst3)
{
    int idx = blockIdx.x * blockDim.x + threadIdx.x;
    if (idx >= N_VOX) return;

    int b = idx >> 21;
    int r = idx & (VOX_PER_B - 1);
    int z = r >> 14;
    int y = (r >> 7) & 127;
    int x = r & 127;

    // own value: fp32 (phi needs precision)
    uint2 pv = src[idx];
    __half2 pv0 = *(const __half2*)&pv.x;
    __half2 pv1 = *(const __half2*)&pv.y;
    float2 f0 = __half22float2(pv0);
    float vz = f0.x, vy = f0.y;
    float vx = __low2float(pv1);

    float phz = (float)z + vz;
    float phy = (float)y + vy;
    float phx = (float)x + vx;

    int iz = __float2int_rd(phz);
    int iy = __float2int_rd(phy);
    int ix = __float2int_rd(phx);
    float wz1 = phz - (float)iz;
    float wy1 = phy - (float)iy;
    float wx1 = phx - (float)ix;
    float wz0 = 1.0f - wz1, wy0 = 1.0f - wy1, wx0 = 1.0f - wx1;

    int z0 = iz & 127, z1 = (iz + 1) & 127;
    int y0 = iy & 127, y1 = (iy + 1) & 127;
    int x0 = ix & 127, x1 = (ix + 1) & 127;

    int base = b << 21;
    int row00 = base + (z0 << 14) + (y0 << 7);
    int row01 = base + (z0 << 14) + (y1 << 7);
    int row10 = base + (z1 << 14) + (y0 << 7);
    int row11 = base + (z1 << 14) + (y1 << 7);
    int rows[4] = { row00, row01, row10, row11 };

    // row weights wz*wy in half2 (broadcast), x weights in half2
    __half2 wzy2[4];
    wzy2[0] = __float2half2_rn(wz0 * wy0);
    wzy2[1] = __float2half2_rn(wz0 * wy1);
    wzy2[2] = __float2half2_rn(wz1 * wy0);
    wzy2[3] = __float2half2_rn(wz1 * wy1);
    __half2 wx2[2];
    wx2[0] = __float2half2_rn(wx0);
    wx2[1] = __float2half2_rn(wx1);
    int xo[2] = { x0, x1 };

    __half2 acc0 = __float2half2_rn(0.f);   // (sz, sy)
    __half2 acc1 = __float2half2_rn(0.f);   // (sx, ·)

#pragma unroll
    for (int rr = 0; rr < 4; ++rr) {
#pragma unroll
        for (int d = 0; d < 2; ++d) {
            uint2 q = __ldg(src + rows[rr] + xo[d]);
            __half2 q0 = *(const __half2*)&q.x;
            __half2 q1 = *(const __half2*)&q.y;
            __half2 w2 = __hmul2(wzy2[rr], wx2[d]);
            acc0 = __hfma2(w2, q0, acc0);
            acc1 = __hfma2(w2, q1, acc1);
        }
    }

    float2 s0 = __half22float2(acc0);
    float sz = s0.x, sy = s0.y;
    float sx = __low2float(acc1);

    float oz = vz + sz;
    float oy = vy + sy;
    float ox = vx + sx;

    if (LAST) {
        float* o = dst3 + (size_t)idx * 3;
        o[0] = oz + (float)z;
        o[1] = oy + (float)y;
        o[2] = ox + (float)x;
    } else {
        dst[idx] = pack_v(oz, oy, ox);
    }
}

extern "C" void kernel_launch(void* const* d_in, const int* in_sizes, int n_in,
                              void* d_out, int out_size)
{
    (void)in_sizes; (void)n_in; (void)out_size;
    const float* vel = (const float*)d_in[0];
    float* out = (float*)d_out;

    uint2* bufA = nullptr;
    uint2* bufB = nullptr;
    cudaGetSymbolAddress((void**)&bufA, g_bufA);
    cudaGetSymbolAddress((void**)&bufB, g_bufB);

    const float scale = 1.0f / 256.0f;   // 1 / 2^STEPS, STEPS = 8
    const int threads = 256;

    convert_kernel<<<(N_VOX / 4 + threads - 1) / threads, threads>>>(vel, bufA, scale);

    const int blocks = (N_VOX + threads - 1) / threads;
    uint2* cur = bufA;
    uint2* nxt = bufB;
    for (int i = 0; i < 7; ++i) {
        gridexp_step<0><<<blocks, threads>>>(cur, nxt, nullptr);
        uint2* t = cur; cur = nxt; nxt = t;
    }
    gridexp_step<1><<<blocks, threads>>>(cur, nullptr, out);
}